// round 5
// baseline (speedup 1.0000x reference)
#include <cuda_runtime.h>
#include <cstdint>

// ---------------------------------------------------------------------------
// GNN: 2-layer GraphSAGE (mean aggr) + global mean pool.
//  N=100000 nodes, E=600000 edges, D=H=O=128, 64 graphs.
//
// Pipeline (one CUDA graph, ~12 kernel launches):
//   1. init zeros (cnt, gsum, gcnt)
//   2. histogram in-degree (int atomics)
//   3-5. exclusive scan of counts -> rowptr (CSR by dst), cursor copy
//   6. bucket-fill edge sources by dst (atomic cursor)
//   7. aggregate layer1: agg = mean_{src in N(dst)} x[src]   (warp/node, no fp atomics)
//   8. dual-GEMM + bias + relu: h1 = relu([agg,x] @ [W1l;W1r] + b1)   (fma.rn.f32x2)
//   9. aggregate layer2: agg = mean h1[src]
//  10. dual-GEMM + bias:       h2 = [agg,h1] @ [W2l;W2r] + b2
//  11. segment pool (batch sorted): gsum/gcnt partial sums + few atomics
//  12. out = gsum / max(gcnt,1)
// ---------------------------------------------------------------------------

#define MAXN 100000
#define MAXE 600000
#define NG   64
#define DD   128

// Scratch (device globals -- no runtime allocation allowed)
__device__ float g_agg[MAXN * DD];
__device__ float g_h1 [MAXN * DD];
__device__ float g_h2 [MAXN * DD];
__device__ int   g_cnt[MAXN];
__device__ int   g_rowptr[MAXN + 1];
__device__ int   g_cursor[MAXN];
__device__ int   g_col[MAXE];
__device__ float g_gsum[NG * DD];
__device__ float g_gcnt[NG];
__device__ int   g_bsums[1024];

// ---------------------------------------------------------------- init zeros
__global__ void k_init(int n) {
    int i = blockIdx.x * blockDim.x + threadIdx.x;
    if (i < n)       g_cnt[i] = 0;
    if (i < NG * DD) g_gsum[i] = 0.0f;
    if (i < NG)      g_gcnt[i] = 0.0f;
}

// ------------------------------------------------------------- degree counts
__global__ void k_count(const int* __restrict__ dst, int e) {
    int i = blockIdx.x * blockDim.x + threadIdx.x;
    if (i < e) atomicAdd(&g_cnt[dst[i]], 1);
}

// ----------------------------------------------------- 2-level exclusive scan
__global__ void k_scan1(int n) {
    __shared__ int s[1024];
    int t = threadIdx.x;
    int i = blockIdx.x * 1024 + t;
    int v = (i < n) ? g_cnt[i] : 0;
    s[t] = v;
    __syncthreads();
    #pragma unroll
    for (int off = 1; off < 1024; off <<= 1) {
        int u = (t >= off) ? s[t - off] : 0;
        __syncthreads();
        s[t] += u;
        __syncthreads();
    }
    if (i < n) g_rowptr[i] = s[t];              // inclusive within block
    if (t == 1023) g_bsums[blockIdx.x] = s[1023];
}

__global__ void k_scan2(int nb) {
    if (threadIdx.x == 0) {
        int run = 0;
        for (int b = 0; b < nb; b++) { int v = g_bsums[b]; g_bsums[b] = run; run += v; }
    }
}

__global__ void k_scan3(int n, int e) {
    int i = blockIdx.x * blockDim.x + threadIdx.x;
    if (i < n) {
        int ex = g_bsums[i >> 10] + g_rowptr[i] - g_cnt[i];  // global exclusive
        g_rowptr[i] = ex;
        g_cursor[i] = ex;
    }
    if (i == 0) g_rowptr[n] = e;
}

// ----------------------------------------------------------- CSR bucket fill
__global__ void k_fill(const int* __restrict__ src, const int* __restrict__ dst, int e) {
    int i = blockIdx.x * blockDim.x + threadIdx.x;
    if (i < e) {
        int d = dst[i];
        int p = atomicAdd(&g_cursor[d], 1);
        g_col[p] = src[i];
    }
}

// -------------------------------------------------- mean aggregation (warp/node)
__global__ void k_agg(const float4* __restrict__ xin, float4* __restrict__ out, int n) {
    int gt = blockIdx.x * blockDim.x + threadIdx.x;
    int node = gt >> 5;
    int lane = gt & 31;
    if (node >= n) return;
    int beg = g_rowptr[node];
    int end = g_rowptr[node + 1];
    float4 acc = make_float4(0.f, 0.f, 0.f, 0.f);
    for (int e = beg; e < end; e++) {
        int j = g_col[e];
        float4 v = __ldg(&xin[j * 32 + lane]);
        acc.x += v.x; acc.y += v.y; acc.z += v.z; acc.w += v.w;
    }
    int deg = end - beg;
    float s = 1.0f / (float)(deg > 0 ? deg : 1);
    acc.x *= s; acc.y *= s; acc.z *= s; acc.w *= s;
    out[node * 32 + lane] = acc;
}

// ------------------------------------------------------- packed f32x2 helpers
__device__ __forceinline__ unsigned long long pack2(float a, float b) {
    unsigned long long r;
    asm("mov.b64 %0, {%1, %2};" : "=l"(r) : "f"(a), "f"(b));
    return r;
}
__device__ __forceinline__ void fma2(unsigned long long& d, unsigned long long a,
                                     unsigned long long b) {
    asm("fma.rn.f32x2 %0, %1, %2, %0;" : "+l"(d) : "l"(a), "l"(b));
}
__device__ __forceinline__ float2 unpack2(unsigned long long v) {
    float2 r;
    asm("mov.b64 {%0, %1}, %2;" : "=f"(r.x), "=f"(r.y) : "l"(v));
    return r;
}

// ------------------------------------------------- dual GEMM: C = [A0,A1]@[B0;B1]+bias
// M-tile 128, N=128, K=256 (two K=128 halves). 256 threads, 8x8 microtile/thread.
template <bool RELU>
__global__ void __launch_bounds__(256)
k_gemm(const float* __restrict__ A0, const float* __restrict__ A1,
       const float* __restrict__ B0, const float* __restrict__ B1,
       const float* __restrict__ bias, float* __restrict__ C, int n) {
    __shared__ __align__(16) float As[16][132];  // [kk][row], padded (2-way max)
    __shared__ __align__(16) float Bs[16][128];  // [kk][col]

    int tid = threadIdx.x;
    int ty = tid >> 4;   // 0..15 -> rows ty*8..+8
    int tx = tid & 15;   // 0..15 -> cols tx*8..+8
    int rowBase = blockIdx.x * 128;

    unsigned long long acc[8][4];
    #pragma unroll
    for (int r = 0; r < 8; r++)
        #pragma unroll
        for (int p = 0; p < 4; p++) acc[r][p] = 0ull;  // bit pattern {0.f,0.f}

    for (int k0 = 0; k0 < 256; k0 += 16) {
        const float* A = (k0 < 128) ? A0 : A1;
        const float* B = (k0 < 128) ? B0 : B1;
        int kb = k0 & 127;

        #pragma unroll
        for (int j = 0; j < 8; j++) {         // A tile: 128 rows x 16 k
            int idx = tid + j * 256;
            int r = idx >> 4, kk = idx & 15;
            int gr = rowBase + r;
            As[kk][r] = (gr < n) ? A[gr * 128 + kb + kk] : 0.0f;
        }
        #pragma unroll
        for (int j = 0; j < 8; j++) {         // B tile: 16 k x 128 cols
            int idx = tid + j * 256;
            int kk = idx >> 7, c = idx & 127;
            Bs[kk][c] = B[(kb + kk) * 128 + c];
        }
        __syncthreads();

        #pragma unroll
        for (int kk = 0; kk < 16; kk++) {
            const float* ar = &As[kk][ty * 8];
            float4 aL = *(const float4*)ar;
            float4 aH = *(const float4*)(ar + 4);
            const unsigned long long* br =
                (const unsigned long long*)&Bs[kk][tx * 8];
            unsigned long long b0 = br[0], b1 = br[1], b2 = br[2], b3 = br[3];
            float av[8] = {aL.x, aL.y, aL.z, aL.w, aH.x, aH.y, aH.z, aH.w};
            #pragma unroll
            for (int r = 0; r < 8; r++) {
                unsigned long long ap = pack2(av[r], av[r]);
                fma2(acc[r][0], ap, b0);
                fma2(acc[r][1], ap, b1);
                fma2(acc[r][2], ap, b2);
                fma2(acc[r][3], ap, b3);
            }
        }
        __syncthreads();
    }

    int colBase = tx * 8;
    #pragma unroll
    for (int r = 0; r < 8; r++) {
        int gr = rowBase + ty * 8 + r;
        if (gr < n) {
            #pragma unroll
            for (int p = 0; p < 4; p++) {
                float2 v = unpack2(acc[r][p]);
                int c = colBase + p * 2;
                v.x += bias[c];
                v.y += bias[c + 1];
                if (RELU) { v.x = fmaxf(v.x, 0.f); v.y = fmaxf(v.y, 0.f); }
                *(float2*)&C[gr * 128 + c] = v;
            }
        }
    }
}

// --------------------------------------------- pooled segment sums (batch sorted)
__global__ void k_pool(const float* __restrict__ h2, const int* __restrict__ batch, int n) {
    const int ROWS = 256;
    int tx = threadIdx.x;           // 128 threads: one per feature column
    int r0 = blockIdx.x * ROWS;
    if (r0 >= n) return;
    int rend = r0 + ROWS; if (rend > n) rend = n;
    float acc = 0.0f;
    int cur = batch[r0];
    int cl = 0;
    for (int r = r0; r < rend; r++) {
        int g = batch[r];
        if (g != cur) {
            atomicAdd(&g_gsum[cur * DD + tx], acc);
            if (tx == 0) atomicAdd(&g_gcnt[cur], (float)cl);
            acc = 0.0f; cl = 0; cur = g;
        }
        acc += h2[r * 128 + tx];
        cl++;
    }
    atomicAdd(&g_gsum[cur * DD + tx], acc);
    if (tx == 0) atomicAdd(&g_gcnt[cur], (float)cl);
}

// ---------------------------------------------------------------- final output
__global__ void k_final(float* __restrict__ out) {
    int i = blockIdx.x * blockDim.x + threadIdx.x;
    if (i < NG * DD) {
        float c = g_gcnt[i >> 7];
        out[i] = g_gsum[i] / fmaxf(c, 1.0f);
    }
}

// ---------------------------------------------------------------------------
extern "C" void kernel_launch(void* const* d_in, const int* in_sizes, int n_in,
                              void* d_out, int out_size) {
    (void)n_in; (void)out_size;
    const float* x     = (const float*)d_in[0];
    const int*   ei    = (const int*)  d_in[1];
    const int*   batch = (const int*)  d_in[2];
    const float* W1l   = (const float*)d_in[3];
    const float* b1    = (const float*)d_in[4];
    const float* W1r   = (const float*)d_in[5];
    const float* W2l   = (const float*)d_in[6];
    const float* b2    = (const float*)d_in[7];
    const float* W2r   = (const float*)d_in[8];
    float*       out   = (float*)d_out;

    int n = in_sizes[0] / 128;   // nodes
    int e = in_sizes[1] / 2;     // edges
    const int* src = ei;         // edge_index[0]
    const int* dst = ei + e;     // edge_index[1]

    void *p_agg, *p_h1, *p_h2;
    cudaGetSymbolAddress(&p_agg, g_agg);
    cudaGetSymbolAddress(&p_h1, g_h1);
    cudaGetSymbolAddress(&p_h2, g_h2);
    float* agg = (float*)p_agg;
    float* h1  = (float*)p_h1;
    float* h2  = (float*)p_h2;

    int nb = (n + 1023) / 1024;

    // CSR build (by dst)
    k_init <<<(n + 255) / 256, 256>>>(n);
    k_count<<<(e + 255) / 256, 256>>>(dst, e);
    k_scan1<<<nb, 1024>>>(n);
    k_scan2<<<1, 32>>>(nb);
    k_scan3<<<(n + 255) / 256, 256>>>(n, e);
    k_fill <<<(e + 255) / 256, 256>>>(src, dst, e);

    int aggBlocks  = (n * 32 + 255) / 256;
    int gemmBlocks = (n + 127) / 128;

    // Layer 1: agg = mean(x[nbr]); h1 = relu([agg,x]@[W1l;W1r] + b1)
    k_agg<<<aggBlocks, 256>>>((const float4*)x, (float4*)agg, n);
    k_gemm<true><<<gemmBlocks, 256>>>(agg, x, W1l, W1r, b1, h1, n);

    // Layer 2: agg = mean(h1[nbr]); h2 = [agg,h1]@[W2l;W2r] + b2
    k_agg<<<aggBlocks, 256>>>((const float4*)h1, (float4*)agg, n);
    k_gemm<false><<<gemmBlocks, 256>>>(agg, h1, W2l, W2r, b2, h2, n);

    // Global mean pool
    k_pool <<<(n + 255) / 256, 128>>>(h2, batch, n);
    k_final<<<(NG * DD + 255) / 256, 256>>>(out);
}

// round 7
// speedup vs baseline: 1.5840x; 1.5840x over previous
#include <cuda_runtime.h>
#include <cuda_bf16.h>
#include <cstdint>

// ---------------------------------------------------------------------------
// GNN: 2-layer GraphSAGE (mean aggr) + global mean pool.
// GEMMs on the tensor pipe via mma.sync.m16n8k16 bf16 (HMMA -- valid on
// compute_103), using split-bf16 3-term decomposition for fp32-grade accuracy.
// Operands stored as packed {bf16 hi, bf16 lo} uint32 pairs.
// ---------------------------------------------------------------------------

#define MAXN 100000
#define MAXE 600000
#define NG   64
#define DD   128

// Scratch (device globals -- no runtime allocation allowed)
__device__ uint32_t g_xp  [MAXN * DD];   // x as pairs
__device__ uint32_t g_aggp[MAXN * DD];   // aggregation output as pairs
__device__ uint32_t g_h1p [MAXN * DD];   // h1 (post-relu) as pairs
__device__ float    g_h2  [MAXN * DD];   // h2 fp32 (for pooling)
__device__ uint32_t g_wt1 [128 * 256];   // [n][k] pairs of stacked [W1l;W1r]
__device__ uint32_t g_wt2 [128 * 256];
__device__ int      g_cnt[MAXN];
__device__ int      g_rowptr[MAXN + 1];
__device__ int      g_cursor[MAXN];
__device__ int      g_col[MAXE];
__device__ float    g_gsum[NG * DD];
__device__ float    g_gcnt[NG];
__device__ int      g_bsums[1024];

// ------------------------------------------------------------- bf16 pair ops
__device__ __forceinline__ uint32_t f2pair(float f) {
    __nv_bfloat16 h = __float2bfloat16(f);
    float hf = __bfloat162float(h);
    __nv_bfloat16 l = __float2bfloat16(f - hf);
    return (uint32_t)__bfloat16_as_ushort(h) |
           ((uint32_t)__bfloat16_as_ushort(l) << 16);
}
__device__ __forceinline__ float pair2f(uint32_t p) {
    float h = __uint_as_float(p << 16);
    float l = __uint_as_float(p & 0xffff0000u);
    return h + l;
}
__device__ __forceinline__ uint32_t prmt(uint32_t a, uint32_t b, uint32_t s) {
    uint32_t r;
    asm("prmt.b32 %0,%1,%2,%3;" : "=r"(r) : "r"(a), "r"(b), "r"(s));
    return r;
}

// --------------------------------------------------------------- PTX helpers
__device__ __forceinline__ uint32_t smem_u32(const void* p) {
    uint32_t a;
    asm("{ .reg .u64 t; cvta.to.shared.u64 t, %1; cvt.u32.u64 %0, t; }"
        : "=r"(a) : "l"(p));
    return a;
}
__device__ __forceinline__ void cpasync16(uint32_t smem, const void* gmem, int sz) {
    asm volatile("cp.async.ca.shared.global [%0], [%1], 16, %2;"
                 :: "r"(smem), "l"(gmem), "r"(sz));
}
__device__ __forceinline__ void cp_commit() {
    asm volatile("cp.async.commit_group;");
}
__device__ __forceinline__ void cp_wait1() {
    asm volatile("cp.async.wait_group 1;");
}
__device__ __forceinline__ void cp_wait0() {
    asm volatile("cp.async.wait_group 0;");
}

// mma.sync m16n8k16, bf16 x bf16 -> f32, accumulate in place
__device__ __forceinline__ void mma_bf16(float (&c)[4],
                                         uint32_t a0, uint32_t a1,
                                         uint32_t a2, uint32_t a3,
                                         uint32_t b0, uint32_t b1) {
    asm volatile(
        "mma.sync.aligned.m16n8k16.row.col.f32.bf16.bf16.f32 "
        "{%0,%1,%2,%3}, {%4,%5,%6,%7}, {%8,%9}, {%0,%1,%2,%3};"
        : "+f"(c[0]), "+f"(c[1]), "+f"(c[2]), "+f"(c[3])
        : "r"(a0), "r"(a1), "r"(a2), "r"(a3), "r"(b0), "r"(b1));
}

// ---------------------------------------------------------------- init zeros
__global__ void k_init(int n) {
    int i = blockIdx.x * blockDim.x + threadIdx.x;
    if (i < n)       g_cnt[i] = 0;
    if (i < NG * DD) g_gsum[i] = 0.0f;
    if (i < NG)      g_gcnt[i] = 0.0f;
}

// ------------------------------------------------------------- degree counts
__global__ void k_count(const int* __restrict__ dst, int e) {
    int i = blockIdx.x * blockDim.x + threadIdx.x;
    if (i < e) atomicAdd(&g_cnt[dst[i]], 1);
}

// ----------------------------------------------------- 2-level exclusive scan
__global__ void k_scan1(int n) {
    __shared__ int s[1024];
    int t = threadIdx.x;
    int i = blockIdx.x * 1024 + t;
    int v = (i < n) ? g_cnt[i] : 0;
    s[t] = v;
    __syncthreads();
    #pragma unroll
    for (int off = 1; off < 1024; off <<= 1) {
        int u = (t >= off) ? s[t - off] : 0;
        __syncthreads();
        s[t] += u;
        __syncthreads();
    }
    if (i < n) g_rowptr[i] = s[t];              // inclusive within block
    if (t == 1023) g_bsums[blockIdx.x] = s[1023];
}

__global__ void k_scan2(int nb) {               // block scan over block sums
    __shared__ int s[1024];
    int t = threadIdx.x;
    int v = (t < nb) ? g_bsums[t] : 0;
    s[t] = v;
    __syncthreads();
    #pragma unroll
    for (int off = 1; off < 1024; off <<= 1) {
        int u = (t >= off) ? s[t - off] : 0;
        __syncthreads();
        s[t] += u;
        __syncthreads();
    }
    if (t < nb) g_bsums[t] = s[t] - v;          // exclusive
}

__global__ void k_scan3(int n, int e) {
    int i = blockIdx.x * blockDim.x + threadIdx.x;
    if (i < n) {
        int ex = g_bsums[i >> 10] + g_rowptr[i] - g_cnt[i];
        g_rowptr[i] = ex;
        g_cursor[i] = ex;
    }
    if (i == 0) g_rowptr[n] = e;
}

// ----------------------------------------------------------- CSR bucket fill
__global__ void k_fill(const int* __restrict__ src, const int* __restrict__ dst, int e) {
    int i = blockIdx.x * blockDim.x + threadIdx.x;
    if (i < e) {
        int d = dst[i];
        int p = atomicAdd(&g_cursor[d], 1);
        g_col[p] = src[i];
    }
}

// ---------------------------------------------------------- fp32 -> pair cvt
__global__ void k_cvt(const float4* __restrict__ x, uint32_t* __restrict__ xp, int tot4) {
    int i = blockIdx.x * blockDim.x + threadIdx.x;
    if (i < tot4) {
        float4 v = x[i];
        uint4 o;
        o.x = f2pair(v.x); o.y = f2pair(v.y); o.z = f2pair(v.z); o.w = f2pair(v.w);
        *(uint4*)&xp[i * 4] = o;
    }
}

// ------------------------------------------- weights -> [n][k] pair array
__global__ void k_cvtw(const float* __restrict__ W1l, const float* __restrict__ W1r,
                       const float* __restrict__ W2l, const float* __restrict__ W2r) {
    int i = blockIdx.x * blockDim.x + threadIdx.x;   // 2 * 128 * 256
    if (i >= 2 * 128 * 256) return;
    int which = i >> 15;
    int idx = i & 32767;
    int nn = idx >> 8;       // output col 0..127
    int k  = idx & 255;      // stacked K 0..255
    float v;
    if (which == 0) v = (k < 128) ? W1l[k * 128 + nn] : W1r[(k - 128) * 128 + nn];
    else            v = (k < 128) ? W2l[k * 128 + nn] : W2r[(k - 128) * 128 + nn];
    uint32_t* wt = which ? g_wt2 : g_wt1;
    wt[nn * 256 + k] = f2pair(v);
}

// -------------------------------------- mean aggregation, fp32 input (layer 1)
__global__ void k_agg_f(const float4* __restrict__ xin, uint32_t* __restrict__ outp, int n) {
    int gt = blockIdx.x * blockDim.x + threadIdx.x;
    int node = gt >> 5;
    int lane = gt & 31;
    if (node >= n) return;
    int beg = g_rowptr[node];
    int end = g_rowptr[node + 1];
    float4 acc = make_float4(0.f, 0.f, 0.f, 0.f);
    for (int e = beg; e < end; e++) {
        int j = g_col[e];
        float4 v = __ldg(&xin[j * 32 + lane]);
        acc.x += v.x; acc.y += v.y; acc.z += v.z; acc.w += v.w;
    }
    int deg = end - beg;
    float s = 1.0f / (float)(deg > 0 ? deg : 1);
    uint4 o;
    o.x = f2pair(acc.x * s); o.y = f2pair(acc.y * s);
    o.z = f2pair(acc.z * s); o.w = f2pair(acc.w * s);
    *(uint4*)&outp[node * 128 + lane * 4] = o;
}

// -------------------------------------- mean aggregation, pair input (layer 2)
__global__ void k_agg_p(const uint4* __restrict__ inp, uint32_t* __restrict__ outp, int n) {
    int gt = blockIdx.x * blockDim.x + threadIdx.x;
    int node = gt >> 5;
    int lane = gt & 31;
    if (node >= n) return;
    int beg = g_rowptr[node];
    int end = g_rowptr[node + 1];
    float4 acc = make_float4(0.f, 0.f, 0.f, 0.f);
    for (int e = beg; e < end; e++) {
        int j = g_col[e];
        uint4 v = __ldg(&inp[j * 32 + lane]);
        acc.x += pair2f(v.x); acc.y += pair2f(v.y);
        acc.z += pair2f(v.z); acc.w += pair2f(v.w);
    }
    int deg = end - beg;
    float s = 1.0f / (float)(deg > 0 ? deg : 1);
    uint4 o;
    o.x = f2pair(acc.x * s); o.y = f2pair(acc.y * s);
    o.z = f2pair(acc.z * s); o.w = f2pair(acc.w * s);
    *(uint4*)&outp[node * 128 + lane * 4] = o;
}

// ------------------------------------------------- split-bf16 HMMA dual GEMM
// C[M=128/blk, N=128] = [A0 | A1](K=256 pairs) @ Bw^T + bias
// 3 MMA terms: AhBh + AhBl + AlBh. K chunks of 32 pairs, cp.async 2-stage.
// smem tile rows padded to 36 uint32 (144B) for near-conflict-free lds.
#define ROWU 36                       // uint32 per smem row
#define STAGE_BYTES (2 * 128 * ROWU * 4)   // A tile + B tile per stage

template <bool RELU, bool PAIR_OUT>
__global__ void __launch_bounds__(256, 2)
k_gemm_mma(const uint32_t* __restrict__ A0, const uint32_t* __restrict__ A1,
           const uint32_t* __restrict__ Bw, const float* __restrict__ bias,
           void* __restrict__ Cout, int n) {
    extern __shared__ __align__(16) unsigned char smraw[];
    uint32_t sbase = smem_u32(smraw);

    int tid = threadIdx.x;
    int wid = tid >> 5;
    int lid = tid & 31;
    int g = lid >> 2;                 // group 0..7
    int t = lid & 3;                  // thread-in-group
    int rowBase = blockIdx.x * 128;
    int rowWarp = (wid >> 1) * 32;    // warp tile: 32 rows x 64 cols
    int colWarp = (wid & 1) * 64;

    float acc[2][8][4];
    #pragma unroll
    for (int rt = 0; rt < 2; rt++)
        #pragma unroll
        for (int ct = 0; ct < 8; ct++)
            #pragma unroll
            for (int q = 0; q < 4; q++) acc[rt][ct][q] = 0.0f;

    // ---- chunk loader (k-chunk c -> stage st) -------------------------------
    auto load_chunk = [&](int c, int st) {
        const uint32_t* Asrc = (c < 4) ? A0 : A1;
        int ko = (c & 3) * 32;            // pair offset within source
        int kb = c * 32;                  // pair offset within stacked K
        uint32_t sA = sbase + st * STAGE_BYTES;
        uint32_t sB = sA + 128 * ROWU * 4;
        #pragma unroll
        for (int j = 0; j < 4; j++) {     // A: 128 rows x 32 pairs = 1024 x16B
            int idx = tid + j * 256;
            int r = idx >> 3, seg = idx & 7;
            int gr = rowBase + r;
            int sz = (gr < n) ? 16 : 0;
            int grc = (gr < n) ? gr : (n - 1);
            cpasync16(sA + r * (ROWU * 4) + seg * 16,
                      Asrc + (size_t)grc * 128 + ko + seg * 4, sz);
        }
        #pragma unroll
        for (int j = 0; j < 4; j++) {     // B: 128 n-rows x 32 pairs
            int idx = tid + j * 256;
            int r = idx >> 3, seg = idx & 7;
            cpasync16(sB + r * (ROWU * 4) + seg * 16,
                      Bw + r * 256 + kb + seg * 4, 16);
        }
        cp_commit();
    };

    load_chunk(0, 0);

    for (int c = 0; c < 8; c++) {
        if (c < 7) { load_chunk(c + 1, (c + 1) & 1); cp_wait1(); }
        else       { cp_wait0(); }
        __syncthreads();

        const uint32_t* sA = (const uint32_t*)(smraw + (c & 1) * STAGE_BYTES);
        const uint32_t* sB = sA + 128 * ROWU;

        #pragma unroll
        for (int kk = 0; kk < 32; kk += 16) {
            uint32_t Ah[2][4], Al[2][4];
            #pragma unroll
            for (int rt = 0; rt < 2; rt++) {
                const uint32_t* p0 = sA + (rowWarp + rt * 16 + g) * ROWU + kk + 2 * t;
                const uint32_t* p1 = p0 + 8 * ROWU;
                uint2 q;
                q = *(const uint2*)p0;
                Ah[rt][0] = prmt(q.x, q.y, 0x5410); Al[rt][0] = prmt(q.x, q.y, 0x7632);
                q = *(const uint2*)p1;
                Ah[rt][1] = prmt(q.x, q.y, 0x5410); Al[rt][1] = prmt(q.x, q.y, 0x7632);
                q = *(const uint2*)(p0 + 8);
                Ah[rt][2] = prmt(q.x, q.y, 0x5410); Al[rt][2] = prmt(q.x, q.y, 0x7632);
                q = *(const uint2*)(p1 + 8);
                Ah[rt][3] = prmt(q.x, q.y, 0x5410); Al[rt][3] = prmt(q.x, q.y, 0x7632);
            }
            #pragma unroll
            for (int ct = 0; ct < 8; ct++) {
                const uint32_t* pb = sB + (colWarp + ct * 8 + g) * ROWU + kk + 2 * t;
                uint2 q0 = *(const uint2*)pb;
                uint2 q1 = *(const uint2*)(pb + 8);
                uint32_t Bh0 = prmt(q0.x, q0.y, 0x5410), Bl0 = prmt(q0.x, q0.y, 0x7632);
                uint32_t Bh1 = prmt(q1.x, q1.y, 0x5410), Bl1 = prmt(q1.x, q1.y, 0x7632);
                #pragma unroll
                for (int rt = 0; rt < 2; rt++) {
                    mma_bf16(acc[rt][ct], Ah[rt][0], Ah[rt][1], Ah[rt][2], Ah[rt][3], Bh0, Bh1);
                    mma_bf16(acc[rt][ct], Ah[rt][0], Ah[rt][1], Ah[rt][2], Ah[rt][3], Bl0, Bl1);
                    mma_bf16(acc[rt][ct], Al[rt][0], Al[rt][1], Al[rt][2], Al[rt][3], Bh0, Bh1);
                }
            }
        }
        __syncthreads();
    }

    // ---- epilogue: bias (+relu), direct stores (32B-sector aligned) ---------
    float bc0[8], bc1[8];
    #pragma unroll
    for (int ct = 0; ct < 8; ct++) {
        int col = colWarp + ct * 8 + 2 * t;
        bc0[ct] = __ldg(&bias[col]);
        bc1[ct] = __ldg(&bias[col + 1]);
    }
    #pragma unroll
    for (int rt = 0; rt < 2; rt++) {
        #pragma unroll
        for (int half = 0; half < 2; half++) {
            int grow = rowBase + rowWarp + rt * 16 + half * 8 + g;
            if (grow >= n) continue;
            #pragma unroll
            for (int ct = 0; ct < 8; ct++) {
                int col = colWarp + ct * 8 + 2 * t;
                float v0 = acc[rt][ct][half * 2 + 0] + bc0[ct];
                float v1 = acc[rt][ct][half * 2 + 1] + bc1[ct];
                if (RELU) { v0 = fmaxf(v0, 0.f); v1 = fmaxf(v1, 0.f); }
                if (PAIR_OUT) {
                    uint2 o; o.x = f2pair(v0); o.y = f2pair(v1);
                    *(uint2*)&((uint32_t*)Cout)[(size_t)grow * 128 + col] = o;
                } else {
                    float2 o; o.x = v0; o.y = v1;
                    *(float2*)&((float*)Cout)[(size_t)grow * 128 + col] = o;
                }
            }
        }
    }
}

// --------------------------------------------- pooled segment sums (batch sorted)
__global__ void k_pool(const float* __restrict__ h2, const int* __restrict__ batch, int n) {
    const int ROWS = 256;
    int tx = threadIdx.x;           // 128 threads: one per feature column
    int r0 = blockIdx.x * ROWS;
    if (r0 >= n) return;
    int rend = r0 + ROWS; if (rend > n) rend = n;
    float acc = 0.0f;
    int cur = batch[r0];
    int cl = 0;
    for (int r = r0; r < rend; r++) {
        int g = batch[r];
        if (g != cur) {
            atomicAdd(&g_gsum[cur * DD + tx], acc);
            if (tx == 0) atomicAdd(&g_gcnt[cur], (float)cl);
            acc = 0.0f; cl = 0; cur = g;
        }
        acc += h2[r * 128 + tx];
        cl++;
    }
    atomicAdd(&g_gsum[cur * DD + tx], acc);
    if (tx == 0) atomicAdd(&g_gcnt[cur], (float)cl);
}

// ---------------------------------------------------------------- final output
__global__ void k_final(float* __restrict__ out) {
    int i = blockIdx.x * blockDim.x + threadIdx.x;
    if (i < NG * DD) {
        float c = g_gcnt[i >> 7];
        out[i] = g_gsum[i] / fmaxf(c, 1.0f);
    }
}

// ---------------------------------------------------------------------------
extern "C" void kernel_launch(void* const* d_in, const int* in_sizes, int n_in,
                              void* d_out, int out_size) {
    (void)n_in; (void)out_size;
    const float* x     = (const float*)d_in[0];
    const int*   ei    = (const int*)  d_in[1];
    const int*   batch = (const int*)  d_in[2];
    const float* W1l   = (const float*)d_in[3];
    const float* b1    = (const float*)d_in[4];
    const float* W1r   = (const float*)d_in[5];
    const float* W2l   = (const float*)d_in[6];
    const float* b2    = (const float*)d_in[7];
    const float* W2r   = (const float*)d_in[8];
    float*       out   = (float*)d_out;

    int n = in_sizes[0] / 128;   // nodes
    int e = in_sizes[1] / 2;     // edges
    const int* src = ei;         // edge_index[0]
    const int* dst = ei + e;     // edge_index[1]

    void *p_xp, *p_aggp, *p_h1p, *p_h2, *p_wt1, *p_wt2;
    cudaGetSymbolAddress(&p_xp,   g_xp);
    cudaGetSymbolAddress(&p_aggp, g_aggp);
    cudaGetSymbolAddress(&p_h1p,  g_h1p);
    cudaGetSymbolAddress(&p_h2,   g_h2);
    cudaGetSymbolAddress(&p_wt1,  g_wt1);
    cudaGetSymbolAddress(&p_wt2,  g_wt2);
    uint32_t* xp   = (uint32_t*)p_xp;
    uint32_t* aggp = (uint32_t*)p_aggp;
    uint32_t* h1p  = (uint32_t*)p_h1p;
    float*    h2   = (float*)p_h2;
    uint32_t* wt1  = (uint32_t*)p_wt1;
    uint32_t* wt2  = (uint32_t*)p_wt2;

    const int GEMM_SMEM = 2 * STAGE_BYTES;   // 73728 B
    cudaFuncSetAttribute(k_gemm_mma<true, true>,
                         cudaFuncAttributeMaxDynamicSharedMemorySize, GEMM_SMEM);
    cudaFuncSetAttribute(k_gemm_mma<false, false>,
                         cudaFuncAttributeMaxDynamicSharedMemorySize, GEMM_SMEM);

    int nb = (n + 1023) / 1024;

    // CSR build (by dst)
    k_init <<<(n + 255) / 256, 256>>>(n);
    k_count<<<(e + 255) / 256, 256>>>(dst, e);
    k_scan1<<<nb, 1024>>>(n);
    k_scan2<<<1, 1024>>>(nb);
    k_scan3<<<(n + 255) / 256, 256>>>(n, e);
    k_fill <<<(e + 255) / 256, 256>>>(src, dst, e);

    // One-time conversions: x -> pairs, weights -> [n][k] pairs
    int tot4 = n * 32;
    k_cvt <<<(tot4 + 255) / 256, 256>>>((const float4*)x, xp, tot4);
    k_cvtw<<<(2 * 128 * 256 + 255) / 256, 256>>>(W1l, W1r, W2l, W2r);

    int aggBlocks  = (n * 32 + 255) / 256;
    int gemmBlocks = (n + 127) / 128;

    // Layer 1: agg = mean(x[nbr]); h1 = relu([agg,x]@[W1l;W1r] + b1)
    k_agg_f<<<aggBlocks, 256>>>((const float4*)x, aggp, n);
    k_gemm_mma<true, true><<<gemmBlocks, 256, GEMM_SMEM>>>(aggp, xp, wt1, b1, h1p, n);

    // Layer 2: agg = mean(h1[nbr]); h2 = [agg,h1]@[W2l;W2r] + b2
    k_agg_p<<<aggBlocks, 256>>>((const uint4*)h1p, aggp, n);
    k_gemm_mma<false, false><<<gemmBlocks, 256, GEMM_SMEM>>>(aggp, h1p, wt2, b2, h2, n);

    // Global mean pool
    k_pool <<<(n + 255) / 256, 128>>>(h2, batch, n);
    k_final<<<(NG * DD + 255) / 256, 256>>>(out);
}